// round 10
// baseline (speedup 1.0000x reference)
#include <cuda_runtime.h>
#include <math.h>

#define BB 2
#define CIN 64
#define CC 64
#define HIN 96
#define HH 48
#define NN 2304
#define KK 7
#define NROWS 4608
#define JSPLIT 12
#define JT_PER 3            /* 36 j-tiles / JSPLIT */

#define KNN_SMEM_BYTES ((128*66 + 64*66 + 128*66) * 4)   /* 84480 */

// ---------------- scratch ----------------
__device__ float g_feat[NROWS*CC];
__device__ float g_sq[NROWS];
__device__ int   g_nbr[NROWS*KK];
__device__ unsigned long long g_cand[(size_t)NROWS*JSPLIT*KK];
__device__ float g_Wh1[NROWS*CC];
__device__ float g_Wh2[NROWS*CC];
__device__ float g_Who[NROWS*CC];
__device__ float g_gT[BB*CC*NN];
__device__ float g_s11[NROWS], g_s21[NROWS], g_s12[NROWS], g_s22[NROWS];
__device__ float g_so1[NROWS], g_so2[NROWS];
__device__ float g_v[512];

// packed dual-lane FMA (Blackwell f32x2) — d += a*b elementwise on 2 floats
__device__ __forceinline__ void ffma2(unsigned long long& d,
                                      unsigned long long a, unsigned long long b) {
    asm("fma.rn.f32x2 %0, %1, %2, %0;" : "+l"(d) : "l"(a), "l"(b));
}

// ---------------- stage 0: fold attention vectors through W ----------------
__global__ void prep_vecs_kernel(const float* __restrict__ W1, const float* __restrict__ a1,
                                 const float* __restrict__ W2, const float* __restrict__ a2,
                                 const float* __restrict__ Wout, const float* __restrict__ aout) {
    int k = threadIdx.x;  // 128
    if (k < 64) {
        float s=0.f,t=0.f,u=0.f,v=0.f;
        for (int f = 0; f < 64; f++) {
            float w1 = W1[k*64+f]; s += w1*a1[f]; t += w1*a1[64+f];
            float w2 = W2[k*64+f]; u += w2*a2[f]; v += w2*a2[64+f];
        }
        g_v[k]=s; g_v[64+k]=t; g_v[128+k]=u; g_v[192+k]=v;
    }
    {
        float s=0.f,t=0.f;
        for (int f = 0; f < 64; f++) {
            float wo = Wout[k*64+f]; s += wo*aout[f]; t += wo*aout[64+f];
        }
        g_v[256+k]=s; g_v[384+k]=t;
    }
}

// ---------------- stage 1: stride-2 conv (1 px x 8 co per thread) ----------------
__global__ void conv_kernel(const float* __restrict__ x, const float* __restrict__ w,
                            const float* __restrict__ bias) {
    __shared__ float ws[8][576];
    int co0 = blockIdx.y * 8;
    for (int idx = threadIdx.x; idx < 8*576; idx += 128)
        ws[idx/576][idx%576] = w[co0*576 + idx];
    __syncthreads();

    int p = blockIdx.x*128 + threadIdx.x;   // [0, 4608)
    int b = p / NN;
    int n = p % NN;
    int ih0 = (n / HH)*2 - 1;
    int iw0 = (n % HH)*2 - 1;

    bool ok[9]; int off[9];
    #pragma unroll
    for (int kh = 0; kh < 3; kh++)
        #pragma unroll
        for (int kw = 0; kw < 3; kw++) {
            int ih = ih0 + kh, iw = iw0 + kw;
            bool o = ((unsigned)ih < HIN) && ((unsigned)iw < HIN);
            ok[kh*3+kw] = o;
            off[kh*3+kw] = o ? (ih*HIN + iw) : 0;
        }

    float acc[8];
    #pragma unroll
    for (int c = 0; c < 8; c++) acc[c] = bias[co0+c];

    const float* xp = x + (size_t)b*64*(HIN*HIN);
    for (int ci = 0; ci < 64; ci++, xp += HIN*HIN) {
        float xv[9];
        #pragma unroll
        for (int q = 0; q < 9; q++) xv[q] = ok[q] ? xp[off[q]] : 0.f;
        #pragma unroll
        for (int q = 0; q < 9; q++) {
            #pragma unroll
            for (int c = 0; c < 8; c++) acc[c] += xv[q]*ws[c][ci*9+q];
        }
    }
    float4* fp = (float4*)&g_feat[(size_t)p*64 + co0];
    fp[0] = make_float4(acc[0], acc[1], acc[2], acc[3]);
    fp[1] = make_float4(acc[4], acc[5], acc[6], acc[7]);
}

// ---------------- stage 2: fused Wh1/Wh2 GEMM + row norms/scores ----------------
__global__ void stats_linear_kernel(const float* __restrict__ W1, const float* __restrict__ W2) {
    __shared__ float sf[16][64];
    int r0 = blockIdx.x*16;
    for (int it = 0; it < 4; it++) {
        int idx = it*256 + threadIdx.x;
        sf[idx >> 6][idx & 63] = g_feat[(size_t)(r0 + (idx >> 6))*64 + (idx & 63)];
    }
    __syncthreads();
    {
        int f = threadIdx.x & 63, rs = threadIdx.x >> 6;
        float a1[4] = {0,0,0,0}, a2[4] = {0,0,0,0};
        #pragma unroll 8
        for (int k = 0; k < 64; k++) {
            float w1 = W1[k*64+f], w2 = W2[k*64+f];
            #pragma unroll
            for (int r = 0; r < 4; r++) {
                float hv = sf[rs*4+r][k];
                a1[r] += hv*w1; a2[r] += hv*w2;
            }
        }
        #pragma unroll
        for (int r = 0; r < 4; r++) {
            int row = r0 + rs*4 + r;
            g_Wh1[(size_t)row*64+f] = a1[r];
            g_Wh2[(size_t)row*64+f] = a2[r];
        }
    }
    {
        int lr = threadIdx.x >> 4, ln = threadIdx.x & 15;
        float p0=0.f,p1=0.f,p2=0.f,p3=0.f,p4=0.f;
        #pragma unroll
        for (int q = 0; q < 4; q++) {
            int k = ln*4 + q;
            float hv = sf[lr][k];
            p0 += hv*hv;
            p1 += hv*g_v[k];      p2 += hv*g_v[64+k];
            p3 += hv*g_v[128+k];  p4 += hv*g_v[192+k];
        }
        #pragma unroll
        for (int off = 8; off; off >>= 1) {
            p0 += __shfl_xor_sync(0xffffffffu, p0, off);
            p1 += __shfl_xor_sync(0xffffffffu, p1, off);
            p2 += __shfl_xor_sync(0xffffffffu, p2, off);
            p3 += __shfl_xor_sync(0xffffffffu, p3, off);
            p4 += __shfl_xor_sync(0xffffffffu, p4, off);
        }
        if (ln == 0) {
            int row = r0 + lr;
            g_sq[row]  = p0;
            g_s11[row] = p1; g_s21[row] = p2;
            g_s12[row] = p3; g_s22[row] = p4;
        }
    }
}

// ---------------- fused dist + top-7: 128x64 tile, 8x4/thread, dynamic smem ----------------
__global__ void __launch_bounds__(256, 2) knn_kernel() {
    extern __shared__ __align__(16) float smem[];
    float (*As)[66] = (float(*)[66])smem;                     // 128 rows
    float (*Bs)[66] = (float(*)[66])(smem + 128*66);          // 64 rows
    float (*Ds)[66] = (float(*)[66])(smem + 128*66 + 64*66);  // 128 rows; later cand
    unsigned long long* cand = (unsigned long long*)&Ds[0][0];  // 14336B < 33792B

    int s = blockIdx.x, itile = blockIdx.y, b = blockIdx.z;
    int i0 = itile*128;
    int t = threadIdx.x;
    for (int q = 0; q < 32; q++) {
        int idx = q*256 + t; int r = idx>>6, c = idx&63;
        As[r][c] = g_feat[(size_t)(b*NN + i0 + r)*64 + c];
    }
    int tx = t&15, ty = t>>4;
    float sqi[8];
    #pragma unroll
    for (int m = 0; m < 8; m++) sqi[m] = g_sq[b*NN + i0 + ty + 16*m];
    int srow = t>>1, sch = t&1;
    float lv[7]; int li[7];
    #pragma unroll
    for (int k = 0; k < 7; k++) { lv[k] = INFINITY; li[k] = 0x7fffffff; }

    for (int jt = 0; jt < JT_PER; jt++) {
        int j0 = (s*JT_PER + jt)*64;
        // load B; overlaps prev selection (selection reads Ds only)
        for (int q = 0; q < 16; q++) {
            int idx = q*256 + t; int r = idx>>6, c = idx&63;
            Bs[r][c] = g_feat[(size_t)(b*NN + j0 + r)*64 + c];
        }
        __syncthreads();                       // Bs ready; prev selection done (Ds free)
        unsigned long long acc2[8][4];
        #pragma unroll
        for (int mi = 0; mi < 8; mi++)
            #pragma unroll
            for (int mj = 0; mj < 4; mj++) acc2[mi][mj] = 0ull;
        #pragma unroll 4
        for (int c2 = 0; c2 < 32; c2++) {
            unsigned long long av[8], bv[4];
            #pragma unroll
            for (int m = 0; m < 8; m++)
                av[m] = *(const unsigned long long*)&As[ty+16*m][2*c2];
            #pragma unroll
            for (int m = 0; m < 4; m++)
                bv[m] = *(const unsigned long long*)&Bs[tx+16*m][2*c2];
            #pragma unroll
            for (int mi = 0; mi < 8; mi++)
                #pragma unroll
                for (int mj = 0; mj < 4; mj++)
                    ffma2(acc2[mi][mj], av[mi], bv[mj]);
        }
        float sqj[4];
        #pragma unroll
        for (int m = 0; m < 4; m++) sqj[m] = g_sq[b*NN + j0 + tx + 16*m];
        #pragma unroll
        for (int mi = 0; mi < 8; mi++)
            #pragma unroll
            for (int mj = 0; mj < 4; mj++) {
                float2 d = *(float2*)&acc2[mi][mj];
                float dot = d.x + d.y;
                Ds[ty+16*mi][tx+16*mj] = fmaxf(sqi[mi] + sqj[mj] - 2.f*dot, 0.f);
            }
        __syncthreads();                       // Ds ready; all GEMM reads of Bs done
        // per-thread candidates arrive in strictly increasing j: strict-< float
        // insertion preserves stable-argsort tie semantics.
        #pragma unroll
        for (int q = 0; q < 32; q++) {
            int jl = sch*32 + q;
            float v = Ds[srow][jl];
            if (v < lv[6]) {
                lv[6] = v; li[6] = j0 + jl;
                #pragma unroll
                for (int p = 6; p > 0; p--) {
                    bool sw = lv[p] < lv[p-1];
                    float tv = lv[p-1]; int ti = li[p-1];
                    lv[p-1] = sw ? lv[p] : lv[p-1];
                    li[p-1] = sw ? li[p] : li[p-1];
                    lv[p]   = sw ? tv : lv[p];
                    li[p]   = sw ? ti : li[p];
                }
            }
        }
    }
    __syncthreads();                           // selections done; Ds free for cand
    #pragma unroll
    for (int k = 0; k < 7; k++)
        cand[srow*14 + sch*7 + k] =
            ((unsigned long long)__float_as_uint(lv[k]) << 32) | (unsigned)li[k];
    __syncthreads();
    if (t < 128) {
        int p0 = 0, p1 = 0;
        unsigned long long* cA = &cand[t*14];
        unsigned long long* go = &g_cand[((size_t)(b*NN + i0 + t)*JSPLIT + s)*KK];
        #pragma unroll
        for (int k = 0; k < KK; k++) {
            unsigned long long v0 = p0 < 7 ? cA[p0] : ~0ull;
            unsigned long long v1 = p1 < 7 ? cA[7+p1] : ~0ull;
            if (v0 < v1) { go[k] = v0; p0++; }
            else         { go[k] = v1; p1++; }
        }
    }
}

__global__ void knn_merge_kernel() {
    int row = blockIdx.x*64 + threadIdx.x;
    if (row >= NROWS) return;
    const unsigned long long* c = &g_cand[(size_t)row*JSPLIT*KK];
    int ptr[JSPLIT];
    #pragma unroll
    for (int q = 0; q < JSPLIT; q++) ptr[q] = 0;
    int bbase = (row / NN) * NN;
    for (int k = 0; k < KK; k++) {
        int bq = 0; unsigned long long bk = ~0ull;
        #pragma unroll
        for (int q = 0; q < JSPLIT; q++) {
            if (ptr[q] < KK) {
                unsigned long long v = c[q*KK + ptr[q]];
                if (v < bk) { bk = v; bq = q; }
            }
        }
        ptr[bq]++;
        g_nbr[row*KK + k] = bbase + (int)(bk & 0xffffffffu);
    }
}

// ---------------- fused: head aggregation + output linear + output scores ----------------
__global__ void gat_fused_kernel(const float* __restrict__ Wout) {
    __shared__ float sf[16][128];
    __shared__ int   jn[16][KK];
    __shared__ float e1[16][KK], e2[16][KK];
    int r0 = blockIdx.x*16;
    int g = threadIdx.x >> 6, f = threadIdx.x & 63;

    #pragma unroll
    for (int rr = 0; rr < 4; rr++) {
        int lr = rr*4 + g;
        int row = r0 + lr;
        if (f < KK) {
            int j = g_nbr[row*KK + f];
            jn[lr][f] = j;
            float v1 = g_s11[row] + g_s21[j];
            float v2 = g_s12[row] + g_s22[j];
            e1[lr][f] = v1 > 0.f ? v1 : 0.2f*v1;
            e2[lr][f] = v2 > 0.f ? v2 : 0.2f*v2;
        }
    }
    __syncthreads();
    #pragma unroll
    for (int rr = 0; rr < 4; rr++) {
        int lr = rr*4 + g;
        float m1 = -INFINITY, m2 = -INFINITY;
        #pragma unroll
        for (int k = 0; k < KK; k++) { m1 = fmaxf(m1, e1[lr][k]); m2 = fmaxf(m2, e2[lr][k]); }
        float w1[KK], w2[KK], s1 = 0.f, s2 = 0.f;
        #pragma unroll
        for (int k = 0; k < KK; k++) {
            w1[k] = expf(e1[lr][k]-m1); s1 += w1[k];
            w2[k] = expf(e2[lr][k]-m2); s2 += w2[k];
        }
        float i1 = 1.f/s1, i2 = 1.f/s2;
        float acc1 = 0.f, acc2 = 0.f;
        #pragma unroll
        for (int k = 0; k < KK; k++) {
            int j = jn[lr][k];
            acc1 += (w1[k]*i1)*g_Wh1[(size_t)j*64+f];
            acc2 += (w2[k]*i2)*g_Wh2[(size_t)j*64+f];
        }
        acc1 = acc1 > 0.f ? acc1 : (expf(acc1)-1.f);
        acc2 = acc2 > 0.f ? acc2 : (expf(acc2)-1.f);
        sf[lr][f]      = acc1;
        sf[lr][64 + f] = acc2;
    }
    __syncthreads();
    {
        int rs = threadIdx.x >> 6;
        float acc[4] = {0,0,0,0};
        #pragma unroll 8
        for (int k = 0; k < 128; k++) {
            float wv = Wout[k*64+f];
            #pragma unroll
            for (int r = 0; r < 4; r++) acc[r] += sf[rs*4+r][k]*wv;
        }
        #pragma unroll
        for (int r = 0; r < 4; r++)
            g_Who[(size_t)(r0 + rs*4 + r)*64+f] = acc[r];
    }
    {
        int lr = threadIdx.x >> 4, ln = threadIdx.x & 15;
        float p1 = 0.f, p2 = 0.f;
        #pragma unroll
        for (int q = 0; q < 8; q++) {
            int k = ln*8 + q;
            float hv = sf[lr][k];
            p1 += hv*g_v[256+k]; p2 += hv*g_v[384+k];
        }
        #pragma unroll
        for (int off = 8; off; off >>= 1) {
            p1 += __shfl_xor_sync(0xffffffffu, p1, off);
            p2 += __shfl_xor_sync(0xffffffffu, p2, off);
        }
        if (ln == 0) {
            g_so1[r0 + lr] = p1;
            g_so2[r0 + lr] = p2;
        }
    }
}

// ---------------- output aggregation -> g_gT ----------------
__global__ void gat_out_kernel() {
    int g = threadIdx.x >> 6, f = threadIdx.x & 63;
    int row = blockIdx.x*4 + g;
    __shared__ int   jn[4][KK];
    __shared__ float ee[4][KK];
    if (f < KK) {
        int j = g_nbr[row*KK + f];
        jn[g][f] = j;
        float v = g_so1[row] + g_so2[j];
        ee[g][f] = v > 0.f ? v : 0.2f*v;
    }
    __syncthreads();
    float mx = -INFINITY;
    #pragma unroll
    for (int k = 0; k < KK; k++) mx = fmaxf(mx, ee[g][k]);
    float wk[KK], sum = 0.f;
    #pragma unroll
    for (int k = 0; k < KK; k++) { wk[k] = expf(ee[g][k]-mx); sum += wk[k]; }
    float inv = 1.f/sum, acc = 0.f;
    #pragma unroll
    for (int k = 0; k < KK; k++) acc += (wk[k]*inv)*g_Who[(size_t)jn[g][k]*64+f];
    acc = acc > 0.f ? acc : (expf(acc)-1.f);
    int b = row / NN, n = row % NN;
    g_gT[(size_t)(b*64 + f)*NN + n] = acc;
}

// ---------------- transpose conv: parity-class blocking + 8-co tiling ----------------
__global__ void tconv_kernel(const float* __restrict__ tw, const float* __restrict__ bias,
                             float* __restrict__ out) {
    __shared__ float ws[8*576];
    int co0 = blockIdx.y*8;
    for (int idx = threadIdx.x; idx < 8*576; idx += 256) {
        int co_l = idx/576, rem = idx%576, ci = rem/9, q = rem%9;
        ws[idx] = tw[((size_t)(ci*64 + co0 + co_l))*9 + q];
    }
    __syncthreads();

    int cls = blockIdx.z;
    int px = cls & 1, py = cls >> 1;
    int p2 = blockIdx.x*256 + threadIdx.x;
    int xw = p2 % HH;
    int yh = (p2 / HH) % HH;
    int b  = p2 / (HH*HH);
    int ow = 2*xw + px, oh = 2*yh + py;

    float acc[8];
    #pragma unroll
    for (int c = 0; c < 8; c++) acc[c] = bias[co0+c];

    const float* gbase = g_gT + (size_t)b*64*NN;
    #pragma unroll
    for (int kh = 0; kh < 3; kh++) {
        int t_ = oh + 1 - kh;
        if (t_ & 1) continue;
        int ih = t_ >> 1; if ((unsigned)ih >= HH) continue;
        #pragma unroll
        for (int kw = 0; kw < 3; kw++) {
            int u = ow + 1 - kw;
            if (u & 1) continue;
            int iw = u >> 1; if ((unsigned)iw >= HH) continue;
            const float* gp = gbase + ih*HH + iw;
            int qq = kh*3 + kw;
            #pragma unroll 8
            for (int ci = 0; ci < 64; ci++) {
                float gv = gp[(size_t)ci*NN];
                #pragma unroll
                for (int c = 0; c < 8; c++) acc[c] += gv * ws[c*576 + ci*9 + qq];
            }
        }
    }
    #pragma unroll
    for (int c = 0; c < 8; c++)
        out[((size_t)(b*64 + co0 + c))*(HIN*HIN) + oh*HIN + ow] = acc[c];
}

// ---------------- launcher ----------------
extern "C" void kernel_launch(void* const* d_in, const int* in_sizes, int n_in,
                              void* d_out, int out_size) {
    const float* x       = (const float*)d_in[0];
    const float* conv_w  = (const float*)d_in[1];
    const float* conv_b  = (const float*)d_in[2];
    const float* W1      = (const float*)d_in[3];
    const float* a1      = (const float*)d_in[4];
    const float* W2      = (const float*)d_in[5];
    const float* a2      = (const float*)d_in[6];
    const float* Wout    = (const float*)d_in[7];
    const float* aout    = (const float*)d_in[8];
    const float* tconv_w = (const float*)d_in[9];
    const float* tconv_b = (const float*)d_in[10];
    float* out = (float*)d_out;

    cudaFuncSetAttribute(knn_kernel, cudaFuncAttributeMaxDynamicSharedMemorySize,
                         KNN_SMEM_BYTES);

    prep_vecs_kernel<<<1, 128>>>(W1, a1, W2, a2, Wout, aout);
    conv_kernel<<<dim3(36, 8), 128>>>(x, conv_w, conv_b);
    stats_linear_kernel<<<NROWS/16, 256>>>(W1, W2);
    knn_kernel<<<dim3(JSPLIT, 18, 2), 256, KNN_SMEM_BYTES>>>();
    knn_merge_kernel<<<NROWS/64, 64>>>();
    gat_fused_kernel<<<NROWS/16, 256>>>(Wout);
    gat_out_kernel<<<NROWS/4, 256>>>();
    tconv_kernel<<<dim3(18, 8, 4), 256>>>(tconv_w, tconv_b, out);
}

// round 12
// speedup vs baseline: 1.0292x; 1.0292x over previous
#include <cuda_runtime.h>
#include <math.h>

#define BB 2
#define CIN 64
#define CC 64
#define HIN 96
#define HH 48
#define NN 2304
#define KK 7
#define NROWS 4608
#define JSPLIT 12
#define JT_PER 3            /* 36 j-tiles / JSPLIT */

#define KNN_SMEM_BYTES ((128*66 + 64*66 + 128*66) * 4)   /* 84480 */

// ---------------- scratch ----------------
__device__ float g_feat[NROWS*CC];
__device__ float g_sq[NROWS];
__device__ int   g_nbr[NROWS*KK];
__device__ unsigned long long g_cand[(size_t)NROWS*JSPLIT*KK];
__device__ float g_Wh1[NROWS*CC];
__device__ float g_Wh2[NROWS*CC];
__device__ float g_Who[NROWS*CC];
__device__ float g_gT[BB*CC*NN];
__device__ float g_s11[NROWS], g_s21[NROWS], g_s12[NROWS], g_s22[NROWS];
__device__ float g_so1[NROWS], g_so2[NROWS];

// packed dual-lane FMA (Blackwell f32x2) — d += a*b elementwise on 2 floats
__device__ __forceinline__ void ffma2(unsigned long long& d,
                                      unsigned long long a, unsigned long long b) {
    asm("fma.rn.f32x2 %0, %1, %2, %0;" : "+l"(d) : "l"(a), "l"(b));
}

// ---------------- stage 1: stride-2 conv (1 px x 8 co per thread, 256 thr) ----------------
__global__ void conv_kernel(const float* __restrict__ x, const float* __restrict__ w,
                            const float* __restrict__ bias) {
    __shared__ float ws[8][576];
    int co0 = blockIdx.y * 8;
    for (int idx = threadIdx.x; idx < 8*576; idx += 256)
        ws[idx/576][idx%576] = w[co0*576 + idx];
    __syncthreads();

    int p = blockIdx.x*256 + threadIdx.x;   // [0, 4608)
    int b = p / NN;
    int n = p % NN;
    int ih0 = (n / HH)*2 - 1;
    int iw0 = (n % HH)*2 - 1;

    bool ok[9]; int off[9];
    #pragma unroll
    for (int kh = 0; kh < 3; kh++)
        #pragma unroll
        for (int kw = 0; kw < 3; kw++) {
            int ih = ih0 + kh, iw = iw0 + kw;
            bool o = ((unsigned)ih < HIN) && ((unsigned)iw < HIN);
            ok[kh*3+kw] = o;
            off[kh*3+kw] = o ? (ih*HIN + iw) : 0;
        }

    float acc[8];
    #pragma unroll
    for (int c = 0; c < 8; c++) acc[c] = bias[co0+c];

    const float* xp = x + (size_t)b*64*(HIN*HIN);
    for (int ci = 0; ci < 64; ci++, xp += HIN*HIN) {
        float xv[9];
        #pragma unroll
        for (int q = 0; q < 9; q++) xv[q] = ok[q] ? xp[off[q]] : 0.f;
        #pragma unroll
        for (int q = 0; q < 9; q++) {
            #pragma unroll
            for (int c = 0; c < 8; c++) acc[c] += xv[q]*ws[c][ci*9+q];
        }
    }
    float4* fp = (float4*)&g_feat[(size_t)p*64 + co0];
    fp[0] = make_float4(acc[0], acc[1], acc[2], acc[3]);
    fp[1] = make_float4(acc[4], acc[5], acc[6], acc[7]);
}

// ---------------- stage 2: Wh1/Wh2 GEMM + row norms/scores (+folded W@a vecs) ----------------
__global__ void stats_linear_kernel(const float* __restrict__ W1, const float* __restrict__ W2,
                                    const float* __restrict__ a1, const float* __restrict__ a2) {
    __shared__ float sf[16][64];
    __shared__ float sv[256];   // v1a[0:64] v1b[64:128] v2a[128:192] v2b[192:256]
    int r0 = blockIdx.x*16;
    for (int it = 0; it < 4; it++) {
        int idx = it*256 + threadIdx.x;
        sf[idx >> 6][idx & 63] = g_feat[(size_t)(r0 + (idx >> 6))*64 + (idx & 63)];
    }
    if (threadIdx.x < 64) {
        int k = threadIdx.x;
        float s=0.f,t=0.f,u=0.f,v=0.f;
        #pragma unroll 8
        for (int f = 0; f < 64; f++) {
            float w1 = W1[k*64+f]; s += w1*a1[f]; t += w1*a1[64+f];
            float w2 = W2[k*64+f]; u += w2*a2[f]; v += w2*a2[64+f];
        }
        sv[k]=s; sv[64+k]=t; sv[128+k]=u; sv[192+k]=v;
    }
    __syncthreads();
    {
        int f = threadIdx.x & 63, rs = threadIdx.x >> 6;
        float a1r[4] = {0,0,0,0}, a2r[4] = {0,0,0,0};
        #pragma unroll 8
        for (int k = 0; k < 64; k++) {
            float w1 = W1[k*64+f], w2 = W2[k*64+f];
            #pragma unroll
            for (int r = 0; r < 4; r++) {
                float hv = sf[rs*4+r][k];
                a1r[r] += hv*w1; a2r[r] += hv*w2;
            }
        }
        #pragma unroll
        for (int r = 0; r < 4; r++) {
            int row = r0 + rs*4 + r;
            g_Wh1[(size_t)row*64+f] = a1r[r];
            g_Wh2[(size_t)row*64+f] = a2r[r];
        }
    }
    {
        int lr = threadIdx.x >> 4, ln = threadIdx.x & 15;
        float p0=0.f,p1=0.f,p2=0.f,p3=0.f,p4=0.f;
        #pragma unroll
        for (int q = 0; q < 4; q++) {
            int k = ln*4 + q;
            float hv = sf[lr][k];
            p0 += hv*hv;
            p1 += hv*sv[k];      p2 += hv*sv[64+k];
            p3 += hv*sv[128+k];  p4 += hv*sv[192+k];
        }
        #pragma unroll
        for (int off = 8; off; off >>= 1) {
            p0 += __shfl_xor_sync(0xffffffffu, p0, off);
            p1 += __shfl_xor_sync(0xffffffffu, p1, off);
            p2 += __shfl_xor_sync(0xffffffffu, p2, off);
            p3 += __shfl_xor_sync(0xffffffffu, p3, off);
            p4 += __shfl_xor_sync(0xffffffffu, p4, off);
        }
        if (ln == 0) {
            int row = r0 + lr;
            g_sq[row]  = p0;
            g_s11[row] = p1; g_s21[row] = p2;
            g_s12[row] = p3; g_s22[row] = p4;
        }
    }
}

// ---------------- fused dist + top-7: 128x64 tile, 8x4/thread, dynamic smem ----------------
__global__ void __launch_bounds__(256, 2) knn_kernel() {
    extern __shared__ __align__(16) float smem[];
    float (*As)[66] = (float(*)[66])smem;                     // 128 rows
    float (*Bs)[66] = (float(*)[66])(smem + 128*66);          // 64 rows
    float (*Ds)[66] = (float(*)[66])(smem + 128*66 + 64*66);  // 128 rows; later cand
    unsigned long long* cand = (unsigned long long*)&Ds[0][0];  // 14336B < 33792B

    int s = blockIdx.x, itile = blockIdx.y, b = blockIdx.z;
    int i0 = itile*128;
    int t = threadIdx.x;
    for (int q = 0; q < 32; q++) {
        int idx = q*256 + t; int r = idx>>6, c = idx&63;
        As[r][c] = g_feat[(size_t)(b*NN + i0 + r)*64 + c];
    }
    int tx = t&15, ty = t>>4;
    float sqi[8];
    #pragma unroll
    for (int m = 0; m < 8; m++) sqi[m] = g_sq[b*NN + i0 + ty + 16*m];
    int srow = t>>1, sch = t&1;
    float lv[7]; int li[7];
    #pragma unroll
    for (int k = 0; k < 7; k++) { lv[k] = INFINITY; li[k] = 0x7fffffff; }

    for (int jt = 0; jt < JT_PER; jt++) {
        int j0 = (s*JT_PER + jt)*64;
        for (int q = 0; q < 16; q++) {
            int idx = q*256 + t; int r = idx>>6, c = idx&63;
            Bs[r][c] = g_feat[(size_t)(b*NN + j0 + r)*64 + c];
        }
        __syncthreads();                       // Bs ready; prev selection done (Ds free)
        unsigned long long acc2[8][4];
        #pragma unroll
        for (int mi = 0; mi < 8; mi++)
            #pragma unroll
            for (int mj = 0; mj < 4; mj++) acc2[mi][mj] = 0ull;
        #pragma unroll 4
        for (int c2 = 0; c2 < 32; c2++) {
            unsigned long long av[8], bv[4];
            #pragma unroll
            for (int m = 0; m < 8; m++)
                av[m] = *(const unsigned long long*)&As[ty+16*m][2*c2];
            #pragma unroll
            for (int m = 0; m < 4; m++)
                bv[m] = *(const unsigned long long*)&Bs[tx+16*m][2*c2];
            #pragma unroll
            for (int mi = 0; mi < 8; mi++)
                #pragma unroll
                for (int mj = 0; mj < 4; mj++)
                    ffma2(acc2[mi][mj], av[mi], bv[mj]);
        }
        float sqj[4];
        #pragma unroll
        for (int m = 0; m < 4; m++) sqj[m] = g_sq[b*NN + j0 + tx + 16*m];
        #pragma unroll
        for (int mi = 0; mi < 8; mi++)
            #pragma unroll
            for (int mj = 0; mj < 4; mj++) {
                float2 d = *(float2*)&acc2[mi][mj];
                float dot = d.x + d.y;
                Ds[ty+16*mi][tx+16*mj] = fmaxf(sqi[mi] + sqj[mj] - 2.f*dot, 0.f);
            }
        __syncthreads();                       // Ds ready; all GEMM reads of Bs done
        // per-thread candidates arrive in strictly increasing j: strict-< float
        // insertion preserves stable-argsort tie semantics.
        #pragma unroll
        for (int q = 0; q < 32; q++) {
            int jl = sch*32 + q;
            float v = Ds[srow][jl];
            if (v < lv[6]) {
                lv[6] = v; li[6] = j0 + jl;
                #pragma unroll
                for (int p = 6; p > 0; p--) {
                    bool sw = lv[p] < lv[p-1];
                    float tv = lv[p-1]; int ti = li[p-1];
                    lv[p-1] = sw ? lv[p] : lv[p-1];
                    li[p-1] = sw ? li[p] : li[p-1];
                    lv[p]   = sw ? tv : lv[p];
                    li[p]   = sw ? ti : li[p];
                }
            }
        }
    }
    __syncthreads();                           // selections done; Ds free for cand
    #pragma unroll
    for (int k = 0; k < 7; k++)
        cand[srow*14 + sch*7 + k] =
            ((unsigned long long)__float_as_uint(lv[k]) << 32) | (unsigned)li[k];
    __syncthreads();
    if (t < 128) {
        int p0 = 0, p1 = 0;
        unsigned long long* cA = &cand[t*14];
        unsigned long long* go = &g_cand[((size_t)(b*NN + i0 + t)*JSPLIT + s)*KK];
        #pragma unroll
        for (int k = 0; k < KK; k++) {
            unsigned long long v0 = p0 < 7 ? cA[p0] : ~0ull;
            unsigned long long v1 = p1 < 7 ? cA[7+p1] : ~0ull;
            if (v0 < v1) { go[k] = v0; p0++; }
            else         { go[k] = v1; p1++; }
        }
    }
}

// ---------------- fused: 12-way knn merge + head agg + output linear + scores ----------------
__global__ void gat_fused_kernel(const float* __restrict__ Wout, const float* __restrict__ aout) {
    __shared__ float sf[16][128];
    __shared__ int   jn[16][KK];
    __shared__ float e1[16][KK], e2[16][KK];
    __shared__ float vo[256];   // vo1[0:128] vo2[128:256]
    int r0 = blockIdx.x*16;
    int g = threadIdx.x >> 6, f = threadIdx.x & 63;

    // fold aout through Wout (threads 0..127)
    if (threadIdx.x < 128) {
        int k = threadIdx.x;
        float s = 0.f, t2 = 0.f;
        #pragma unroll 8
        for (int ff = 0; ff < 64; ff++) {
            float wo = Wout[k*64+ff];
            s += wo*aout[ff]; t2 += wo*aout[64+ff];
        }
        vo[k] = s; vo[128+k] = t2;
    }
    // 12-way candidate merge for this block's 16 rows (threads 128..143)
    if (threadIdx.x >= 128 && threadIdx.x < 144) {
        int lr = threadIdx.x - 128;
        int row = r0 + lr;
        const unsigned long long* c = &g_cand[(size_t)row*JSPLIT*KK];
        int ptr[JSPLIT];
        #pragma unroll
        for (int q = 0; q < JSPLIT; q++) ptr[q] = 0;
        int bbase = (row / NN) * NN;
        for (int k = 0; k < KK; k++) {
            int bq = 0; unsigned long long bk = ~0ull;
            #pragma unroll
            for (int q = 0; q < JSPLIT; q++) {
                if (ptr[q] < KK) {
                    unsigned long long v = c[q*KK + ptr[q]];
                    if (v < bk) { bk = v; bq = q; }
                }
            }
            ptr[bq]++;
            int j = bbase + (int)(bk & 0xffffffffu);
            jn[lr][k] = j;
            g_nbr[row*KK + k] = j;             // for gat_out
        }
    }
    __syncthreads();

    #pragma unroll
    for (int rr = 0; rr < 4; rr++) {
        int lr = rr*4 + g;
        int row = r0 + lr;
        if (f < KK) {
            int j = jn[lr][f];
            float v1 = g_s11[row] + g_s21[j];
            float v2 = g_s12[row] + g_s22[j];
            e1[lr][f] = v1 > 0.f ? v1 : 0.2f*v1;
            e2[lr][f] = v2 > 0.f ? v2 : 0.2f*v2;
        }
    }
    __syncthreads();
    #pragma unroll
    for (int rr = 0; rr < 4; rr++) {
        int lr = rr*4 + g;
        float m1 = -INFINITY, m2 = -INFINITY;
        #pragma unroll
        for (int k = 0; k < KK; k++) { m1 = fmaxf(m1, e1[lr][k]); m2 = fmaxf(m2, e2[lr][k]); }
        float w1[KK], w2[KK], s1 = 0.f, s2 = 0.f;
        #pragma unroll
        for (int k = 0; k < KK; k++) {
            w1[k] = expf(e1[lr][k]-m1); s1 += w1[k];
            w2[k] = expf(e2[lr][k]-m2); s2 += w2[k];
        }
        float i1 = 1.f/s1, i2 = 1.f/s2;
        float acc1 = 0.f, acc2 = 0.f;
        #pragma unroll
        for (int k = 0; k < KK; k++) {
            int j = jn[lr][k];
            acc1 += (w1[k]*i1)*g_Wh1[(size_t)j*64+f];
            acc2 += (w2[k]*i2)*g_Wh2[(size_t)j*64+f];
        }
        acc1 = acc1 > 0.f ? acc1 : (expf(acc1)-1.f);
        acc2 = acc2 > 0.f ? acc2 : (expf(acc2)-1.f);
        sf[lr][f]      = acc1;
        sf[lr][64 + f] = acc2;
    }
    __syncthreads();
    {
        int rs = threadIdx.x >> 6;
        float acc[4] = {0,0,0,0};
        #pragma unroll 8
        for (int k = 0; k < 128; k++) {
            float wv = Wout[k*64+f];
            #pragma unroll
            for (int r = 0; r < 4; r++) acc[r] += sf[rs*4+r][k]*wv;
        }
        #pragma unroll
        for (int r = 0; r < 4; r++)
            g_Who[(size_t)(r0 + rs*4 + r)*64+f] = acc[r];
    }
    {
        int lr = threadIdx.x >> 4, ln = threadIdx.x & 15;
        float p1 = 0.f, p2 = 0.f;
        #pragma unroll
        for (int q = 0; q < 8; q++) {
            int k = ln*8 + q;
            float hv = sf[lr][k];
            p1 += hv*vo[k]; p2 += hv*vo[128+k];
        }
        #pragma unroll
        for (int off = 8; off; off >>= 1) {
            p1 += __shfl_xor_sync(0xffffffffu, p1, off);
            p2 += __shfl_xor_sync(0xffffffffu, p2, off);
        }
        if (ln == 0) {
            g_so1[r0 + lr] = p1;
            g_so2[r0 + lr] = p2;
        }
    }
}

// ---------------- output aggregation -> g_gT ----------------
__global__ void gat_out_kernel() {
    int g = threadIdx.x >> 6, f = threadIdx.x & 63;
    int row = blockIdx.x*4 + g;
    __shared__ int   jn[4][KK];
    __shared__ float ee[4][KK];
    if (f < KK) {
        int j = g_nbr[row*KK + f];
        jn[g][f] = j;
        float v = g_so1[row] + g_so2[j];
        ee[g][f] = v > 0.f ? v : 0.2f*v;
    }
    __syncthreads();
    float mx = -INFINITY;
    #pragma unroll
    for (int k = 0; k < KK; k++) mx = fmaxf(mx, ee[g][k]);
    float wk[KK], sum = 0.f;
    #pragma unroll
    for (int k = 0; k < KK; k++) { wk[k] = expf(ee[g][k]-mx); sum += wk[k]; }
    float inv = 1.f/sum, acc = 0.f;
    #pragma unroll
    for (int k = 0; k < KK; k++) acc += (wk[k]*inv)*g_Who[(size_t)jn[g][k]*64+f];
    acc = acc > 0.f ? acc : (expf(acc)-1.f);
    int b = row / NN, n = row % NN;
    g_gT[(size_t)(b*64 + f)*NN + n] = acc;
}

// ---------------- transpose conv: parity-class blocking + 8-co tiling ----------------
__global__ void tconv_kernel(const float* __restrict__ tw, const float* __restrict__ bias,
                             float* __restrict__ out) {
    __shared__ float ws[8*576];
    int co0 = blockIdx.y*8;
    for (int idx = threadIdx.x; idx < 8*576; idx += 256) {
        int co_l = idx/576, rem = idx%576, ci = rem/9, q = rem%9;
        ws[idx] = tw[((size_t)(ci*64 + co0 + co_l))*9 + q];
    }
    __syncthreads();

    int cls = blockIdx.z;
    int px = cls & 1, py = cls >> 1;
    int p2 = blockIdx.x*256 + threadIdx.x;
    int xw = p2 % HH;
    int yh = (p2 / HH) % HH;
    int b  = p2 / (HH*HH);
    int ow = 2*xw + px, oh = 2*yh + py;

    float acc[8];
    #pragma unroll
    for (int c = 0; c < 8; c++) acc[c] = bias[co0+c];

    const float* gbase = g_gT + (size_t)b*64*NN;
    #pragma unroll
    for (int kh = 0; kh < 3; kh++) {
        int t_ = oh + 1 - kh;
        if (t_ & 1) continue;
        int ih = t_ >> 1; if ((unsigned)ih >= HH) continue;
        #pragma unroll
        for (int kw = 0; kw < 3; kw++) {
            int u = ow + 1 - kw;
            if (u & 1) continue;
            int iw = u >> 1; if ((unsigned)iw >= HH) continue;
            const float* gp = gbase + ih*HH + iw;
            int qq = kh*3 + kw;
            #pragma unroll 8
            for (int ci = 0; ci < 64; ci++) {
                float gv = gp[(size_t)ci*NN];
                #pragma unroll
                for (int c = 0; c < 8; c++) acc[c] += gv * ws[c*576 + ci*9 + qq];
            }
        }
    }
    #pragma unroll
    for (int c = 0; c < 8; c++)
        out[((size_t)(b*64 + co0 + c))*(HIN*HIN) + oh*HIN + ow] = acc[c];
}

// ---------------- launcher ----------------
extern "C" void kernel_launch(void* const* d_in, const int* in_sizes, int n_in,
                              void* d_out, int out_size) {
    const float* x       = (const float*)d_in[0];
    const float* conv_w  = (const float*)d_in[1];
    const float* conv_b  = (const float*)d_in[2];
    const float* W1      = (const float*)d_in[3];
    const float* a1      = (const float*)d_in[4];
    const float* W2      = (const float*)d_in[5];
    const float* a2      = (const float*)d_in[6];
    const float* Wout    = (const float*)d_in[7];
    const float* aout    = (const float*)d_in[8];
    const float* tconv_w = (const float*)d_in[9];
    const float* tconv_b = (const float*)d_in[10];
    float* out = (float*)d_out;

    cudaFuncSetAttribute(knn_kernel, cudaFuncAttributeMaxDynamicSharedMemorySize,
                         KNN_SMEM_BYTES);

    conv_kernel<<<dim3(18, 8), 256>>>(x, conv_w, conv_b);
    stats_linear_kernel<<<NROWS/16, 256>>>(W1, W2, a1, a2);
    knn_kernel<<<dim3(JSPLIT, 18, 2), 256, KNN_SMEM_BYTES>>>();
    gat_fused_kernel<<<NROWS/16, 256>>>(Wout, aout);
    gat_out_kernel<<<NROWS/4, 256>>>();
    tconv_kernel<<<dim3(18, 8, 4), 256>>>(tconv_w, tconv_b, out);
}

// round 13
// speedup vs baseline: 1.0538x; 1.0238x over previous
#include <cuda_runtime.h>
#include <math.h>

#define BB 2
#define CIN 64
#define CC 64
#define HIN 96
#define HH 48
#define NN 2304
#define KK 7
#define NROWS 4608
#define JSPLIT 12
#define JT_PER 3            /* 36 j-tiles / JSPLIT */

#define KNN_SMEM_BYTES ((128*66 + 64*66 + 128*66) * 4)   /* 84480 */

// ---------------- scratch ----------------
__device__ float g_feat[NROWS*CC];
__device__ float g_sq[NROWS];
__device__ int   g_nbr[NROWS*KK];
__device__ unsigned long long g_cand[(size_t)NROWS*JSPLIT*KK];
__device__ float g_Wh1[NROWS*CC];
__device__ float g_Wh2[NROWS*CC];
__device__ float g_Who[NROWS*CC];
__device__ float g_gT[BB*CC*NN];
__device__ float g_s11[NROWS], g_s21[NROWS], g_s12[NROWS], g_s22[NROWS];
__device__ float g_so1[NROWS], g_so2[NROWS];
__device__ float g_vo[256];   // vo1[0:128] vo2[128:256]

// packed dual-lane FMA (Blackwell f32x2) — d += a*b elementwise on 2 floats
__device__ __forceinline__ void ffma2(unsigned long long& d,
                                      unsigned long long a, unsigned long long b) {
    asm("fma.rn.f32x2 %0, %1, %2, %0;" : "+l"(d) : "l"(a), "l"(b));
}

// ---------------- stage 1: stride-2 conv (1 px x 8 co per thread, 256 thr) ----------------
__global__ void conv_kernel(const float* __restrict__ x, const float* __restrict__ w,
                            const float* __restrict__ bias) {
    __shared__ float ws[8][576];
    int co0 = blockIdx.y * 8;
    for (int idx = threadIdx.x; idx < 8*576; idx += 256)
        ws[idx/576][idx%576] = w[co0*576 + idx];
    __syncthreads();

    int p = blockIdx.x*256 + threadIdx.x;   // [0, 4608)
    int b = p / NN;
    int n = p % NN;
    int ih0 = (n / HH)*2 - 1;
    int iw0 = (n % HH)*2 - 1;

    bool ok[9]; int off[9];
    #pragma unroll
    for (int kh = 0; kh < 3; kh++)
        #pragma unroll
        for (int kw = 0; kw < 3; kw++) {
            int ih = ih0 + kh, iw = iw0 + kw;
            bool o = ((unsigned)ih < HIN) && ((unsigned)iw < HIN);
            ok[kh*3+kw] = o;
            off[kh*3+kw] = o ? (ih*HIN + iw) : 0;
        }

    float acc[8];
    #pragma unroll
    for (int c = 0; c < 8; c++) acc[c] = bias[co0+c];

    const float* xp = x + (size_t)b*64*(HIN*HIN);
    for (int ci = 0; ci < 64; ci++, xp += HIN*HIN) {
        float xv[9];
        #pragma unroll
        for (int q = 0; q < 9; q++) xv[q] = ok[q] ? xp[off[q]] : 0.f;
        #pragma unroll
        for (int q = 0; q < 9; q++) {
            #pragma unroll
            for (int c = 0; c < 8; c++) acc[c] += xv[q]*ws[c][ci*9+q];
        }
    }
    float4* fp = (float4*)&g_feat[(size_t)p*64 + co0];
    fp[0] = make_float4(acc[0], acc[1], acc[2], acc[3]);
    fp[1] = make_float4(acc[4], acc[5], acc[6], acc[7]);
}

// ---------------- stage 2: Wh1/Wh2 GEMM + row norms/scores (+folded vecs) ----------------
__global__ void stats_linear_kernel(const float* __restrict__ W1, const float* __restrict__ W2,
                                    const float* __restrict__ a1, const float* __restrict__ a2,
                                    const float* __restrict__ Wout, const float* __restrict__ aout) {
    __shared__ float sf[16][64];
    __shared__ float sv[256];   // v1a[0:64] v1b[64:128] v2a[128:192] v2b[192:256]
    int r0 = blockIdx.x*16;
    for (int it = 0; it < 4; it++) {
        int idx = it*256 + threadIdx.x;
        sf[idx >> 6][idx & 63] = g_feat[(size_t)(r0 + (idx >> 6))*64 + (idx & 63)];
    }
    if (threadIdx.x < 64) {
        int k = threadIdx.x;
        float s=0.f,t=0.f,u=0.f,v=0.f;
        #pragma unroll 8
        for (int f = 0; f < 64; f++) {
            float w1 = W1[k*64+f]; s += w1*a1[f]; t += w1*a1[64+f];
            float w2 = W2[k*64+f]; u += w2*a2[f]; v += w2*a2[64+f];
        }
        sv[k]=s; sv[64+k]=t; sv[128+k]=u; sv[192+k]=v;
    }
    // block 0 additionally folds aout through Wout into g_vo (once for whole grid)
    if (blockIdx.x == 0 && threadIdx.x >= 128) {
        int k = threadIdx.x - 128;
        float s = 0.f, t2 = 0.f;
        #pragma unroll 8
        for (int ff = 0; ff < 64; ff++) {
            float wo = Wout[k*64+ff];
            s += wo*aout[ff]; t2 += wo*aout[64+ff];
        }
        g_vo[k] = s; g_vo[128+k] = t2;
    }
    __syncthreads();
    {
        int f = threadIdx.x & 63, rs = threadIdx.x >> 6;
        float a1r[4] = {0,0,0,0}, a2r[4] = {0,0,0,0};
        #pragma unroll 8
        for (int k = 0; k < 64; k++) {
            float w1 = W1[k*64+f], w2 = W2[k*64+f];
            #pragma unroll
            for (int r = 0; r < 4; r++) {
                float hv = sf[rs*4+r][k];
                a1r[r] += hv*w1; a2r[r] += hv*w2;
            }
        }
        #pragma unroll
        for (int r = 0; r < 4; r++) {
            int row = r0 + rs*4 + r;
            g_Wh1[(size_t)row*64+f] = a1r[r];
            g_Wh2[(size_t)row*64+f] = a2r[r];
        }
    }
    {
        int lr = threadIdx.x >> 4, ln = threadIdx.x & 15;
        float p0=0.f,p1=0.f,p2=0.f,p3=0.f,p4=0.f;
        #pragma unroll
        for (int q = 0; q < 4; q++) {
            int k = ln*4 + q;
            float hv = sf[lr][k];
            p0 += hv*hv;
            p1 += hv*sv[k];      p2 += hv*sv[64+k];
            p3 += hv*sv[128+k];  p4 += hv*sv[192+k];
        }
        #pragma unroll
        for (int off = 8; off; off >>= 1) {
            p0 += __shfl_xor_sync(0xffffffffu, p0, off);
            p1 += __shfl_xor_sync(0xffffffffu, p1, off);
            p2 += __shfl_xor_sync(0xffffffffu, p2, off);
            p3 += __shfl_xor_sync(0xffffffffu, p3, off);
            p4 += __shfl_xor_sync(0xffffffffu, p4, off);
        }
        if (ln == 0) {
            int row = r0 + lr;
            g_sq[row]  = p0;
            g_s11[row] = p1; g_s21[row] = p2;
            g_s12[row] = p3; g_s22[row] = p4;
        }
    }
}

// ---------------- fused dist + top-7: 128x64 tile, 8x4/thread, dynamic smem ----------------
__global__ void __launch_bounds__(256, 2) knn_kernel() {
    extern __shared__ __align__(16) float smem[];
    float (*As)[66] = (float(*)[66])smem;                     // 128 rows
    float (*Bs)[66] = (float(*)[66])(smem + 128*66);          // 64 rows
    float (*Ds)[66] = (float(*)[66])(smem + 128*66 + 64*66);  // 128 rows; later cand
    unsigned long long* cand = (unsigned long long*)&Ds[0][0];  // 14336B < 33792B

    int s = blockIdx.x, itile = blockIdx.y, b = blockIdx.z;
    int i0 = itile*128;
    int t = threadIdx.x;
    for (int q = 0; q < 32; q++) {
        int idx = q*256 + t; int r = idx>>6, c = idx&63;
        As[r][c] = g_feat[(size_t)(b*NN + i0 + r)*64 + c];
    }
    int tx = t&15, ty = t>>4;
    float sqi[8];
    #pragma unroll
    for (int m = 0; m < 8; m++) sqi[m] = g_sq[b*NN + i0 + ty + 16*m];
    int srow = t>>1, sch = t&1;
    float lv[7]; int li[7];
    #pragma unroll
    for (int k = 0; k < 7; k++) { lv[k] = INFINITY; li[k] = 0x7fffffff; }

    for (int jt = 0; jt < JT_PER; jt++) {
        int j0 = (s*JT_PER + jt)*64;
        for (int q = 0; q < 16; q++) {
            int idx = q*256 + t; int r = idx>>6, c = idx&63;
            Bs[r][c] = g_feat[(size_t)(b*NN + j0 + r)*64 + c];
        }
        __syncthreads();                       // Bs ready; prev selection done (Ds free)
        unsigned long long acc2[8][4];
        #pragma unroll
        for (int mi = 0; mi < 8; mi++)
            #pragma unroll
            for (int mj = 0; mj < 4; mj++) acc2[mi][mj] = 0ull;
        #pragma unroll 4
        for (int c2 = 0; c2 < 32; c2++) {
            unsigned long long av[8], bv[4];
            #pragma unroll
            for (int m = 0; m < 8; m++)
                av[m] = *(const unsigned long long*)&As[ty+16*m][2*c2];
            #pragma unroll
            for (int m = 0; m < 4; m++)
                bv[m] = *(const unsigned long long*)&Bs[tx+16*m][2*c2];
            #pragma unroll
            for (int mi = 0; mi < 8; mi++)
                #pragma unroll
                for (int mj = 0; mj < 4; mj++)
                    ffma2(acc2[mi][mj], av[mi], bv[mj]);
        }
        float sqj[4];
        #pragma unroll
        for (int m = 0; m < 4; m++) sqj[m] = g_sq[b*NN + j0 + tx + 16*m];
        #pragma unroll
        for (int mi = 0; mi < 8; mi++)
            #pragma unroll
            for (int mj = 0; mj < 4; mj++) {
                float2 d = *(float2*)&acc2[mi][mj];
                float dot = d.x + d.y;
                Ds[ty+16*mi][tx+16*mj] = fmaxf(sqi[mi] + sqj[mj] - 2.f*dot, 0.f);
            }
        __syncthreads();                       // Ds ready; all GEMM reads of Bs done
        // per-thread candidates arrive in strictly increasing j: strict-< float
        // insertion preserves stable-argsort tie semantics.
        #pragma unroll
        for (int q = 0; q < 32; q++) {
            int jl = sch*32 + q;
            float v = Ds[srow][jl];
            if (v < lv[6]) {
                lv[6] = v; li[6] = j0 + jl;
                #pragma unroll
                for (int p = 6; p > 0; p--) {
                    bool sw = lv[p] < lv[p-1];
                    float tv = lv[p-1]; int ti = li[p-1];
                    lv[p-1] = sw ? lv[p] : lv[p-1];
                    li[p-1] = sw ? li[p] : li[p-1];
                    lv[p]   = sw ? tv : lv[p];
                    li[p]   = sw ? ti : li[p];
                }
            }
        }
    }
    __syncthreads();                           // selections done; Ds free for cand
    #pragma unroll
    for (int k = 0; k < 7; k++)
        cand[srow*14 + sch*7 + k] =
            ((unsigned long long)__float_as_uint(lv[k]) << 32) | (unsigned)li[k];
    __syncthreads();
    if (t < 128) {
        int p0 = 0, p1 = 0;
        unsigned long long* cA = &cand[t*14];
        unsigned long long* go = &g_cand[((size_t)(b*NN + i0 + t)*JSPLIT + s)*KK];
        #pragma unroll
        for (int k = 0; k < KK; k++) {
            unsigned long long v0 = p0 < 7 ? cA[p0] : ~0ull;
            unsigned long long v1 = p1 < 7 ? cA[7+p1] : ~0ull;
            if (v0 < v1) { go[k] = v0; p0++; }
            else         { go[k] = v1; p1++; }
        }
    }
}

// ---------------- fused: knn merge (smem-staged) + head agg + out linear + scores ----------------
__global__ void gat_fused_kernel(const float* __restrict__ Wout) {
    __shared__ float sf[16][128];
    __shared__ int   jn[16][KK];
    __shared__ float e1[16][KK], e2[16][KK];
    __shared__ float vo[256];
    __shared__ unsigned long long sc[16][JSPLIT*KK];   // 16x84 u64 = 10752B
    int r0 = blockIdx.x*16;
    int g = threadIdx.x >> 6, f = threadIdx.x & 63;

    // parallel coalesced staging of candidates (16 rows x 84)
    for (int i = threadIdx.x; i < 16*JSPLIT*KK; i += 256)
        sc[i/(JSPLIT*KK)][i%(JSPLIT*KK)] = g_cand[(size_t)r0*JSPLIT*KK + i];
    if (threadIdx.x < 256) {
        // load precomputed vo
        if (threadIdx.x < 256) vo[threadIdx.x] = g_vo[threadIdx.x];
    }
    __syncthreads();

    // 12-way merge from smem (threads 0..15, one row each)
    if (threadIdx.x < 16) {
        int lr = threadIdx.x;
        int row = r0 + lr;
        int ptr[JSPLIT];
        #pragma unroll
        for (int q = 0; q < JSPLIT; q++) ptr[q] = 0;
        int bbase = (row / NN) * NN;
        for (int k = 0; k < KK; k++) {
            int bq = 0; unsigned long long bk = ~0ull;
            #pragma unroll
            for (int q = 0; q < JSPLIT; q++) {
                if (ptr[q] < KK) {
                    unsigned long long v = sc[lr][q*KK + ptr[q]];
                    if (v < bk) { bk = v; bq = q; }
                }
            }
            ptr[bq]++;
            int j = bbase + (int)(bk & 0xffffffffu);
            jn[lr][k] = j;
            g_nbr[row*KK + k] = j;             // for gat_out
        }
    }
    __syncthreads();

    #pragma unroll
    for (int rr = 0; rr < 4; rr++) {
        int lr = rr*4 + g;
        int row = r0 + lr;
        if (f < KK) {
            int j = jn[lr][f];
            float v1 = g_s11[row] + g_s21[j];
            float v2 = g_s12[row] + g_s22[j];
            e1[lr][f] = v1 > 0.f ? v1 : 0.2f*v1;
            e2[lr][f] = v2 > 0.f ? v2 : 0.2f*v2;
        }
    }
    __syncthreads();
    #pragma unroll
    for (int rr = 0; rr < 4; rr++) {
        int lr = rr*4 + g;
        float m1 = -INFINITY, m2 = -INFINITY;
        #pragma unroll
        for (int k = 0; k < KK; k++) { m1 = fmaxf(m1, e1[lr][k]); m2 = fmaxf(m2, e2[lr][k]); }
        float w1[KK], w2[KK], s1 = 0.f, s2 = 0.f;
        #pragma unroll
        for (int k = 0; k < KK; k++) {
            w1[k] = expf(e1[lr][k]-m1); s1 += w1[k];
            w2[k] = expf(e2[lr][k]-m2); s2 += w2[k];
        }
        float i1 = 1.f/s1, i2 = 1.f/s2;
        float acc1 = 0.f, acc2 = 0.f;
        #pragma unroll
        for (int k = 0; k < KK; k++) {
            int j = jn[lr][k];
            acc1 += (w1[k]*i1)*g_Wh1[(size_t)j*64+f];
            acc2 += (w2[k]*i2)*g_Wh2[(size_t)j*64+f];
        }
        acc1 = acc1 > 0.f ? acc1 : (expf(acc1)-1.f);
        acc2 = acc2 > 0.f ? acc2 : (expf(acc2)-1.f);
        sf[lr][f]      = acc1;
        sf[lr][64 + f] = acc2;
    }
    __syncthreads();
    {
        int rs = threadIdx.x >> 6;
        float acc[4] = {0,0,0,0};
        #pragma unroll 8
        for (int k = 0; k < 128; k++) {
            float wv = Wout[k*64+f];
            #pragma unroll
            for (int r = 0; r < 4; r++) acc[r] += sf[rs*4+r][k]*wv;
        }
        #pragma unroll
        for (int r = 0; r < 4; r++)
            g_Who[(size_t)(r0 + rs*4 + r)*64+f] = acc[r];
    }
    {
        int lr = threadIdx.x >> 4, ln = threadIdx.x & 15;
        float p1 = 0.f, p2 = 0.f;
        #pragma unroll
        for (int q = 0; q < 8; q++) {
            int k = ln*8 + q;
            float hv = sf[lr][k];
            p1 += hv*vo[k]; p2 += hv*vo[128+k];
        }
        #pragma unroll
        for (int off = 8; off; off >>= 1) {
            p1 += __shfl_xor_sync(0xffffffffu, p1, off);
            p2 += __shfl_xor_sync(0xffffffffu, p2, off);
        }
        if (ln == 0) {
            g_so1[r0 + lr] = p1;
            g_so2[r0 + lr] = p2;
        }
    }
}

// ---------------- output aggregation -> g_gT ----------------
__global__ void gat_out_kernel() {
    int g = threadIdx.x >> 6, f = threadIdx.x & 63;
    int row = blockIdx.x*4 + g;
    __shared__ int   jn[4][KK];
    __shared__ float ee[4][KK];
    if (f < KK) {
        int j = g_nbr[row*KK + f];
        jn[g][f] = j;
        float v = g_so1[row] + g_so2[j];
        ee[g][f] = v > 0.f ? v : 0.2f*v;
    }
    __syncthreads();
    float mx = -INFINITY;
    #pragma unroll
    for (int k = 0; k < KK; k++) mx = fmaxf(mx, ee[g][k]);
    float wk[KK], sum = 0.f;
    #pragma unroll
    for (int k = 0; k < KK; k++) { wk[k] = expf(ee[g][k]-mx); sum += wk[k]; }
    float inv = 1.f/sum, acc = 0.f;
    #pragma unroll
    for (int k = 0; k < KK; k++) acc += (wk[k]*inv)*g_Who[(size_t)jn[g][k]*64+f];
    acc = acc > 0.f ? acc : (expf(acc)-1.f);
    int b = row / NN, n = row % NN;
    g_gT[(size_t)(b*64 + f)*NN + n] = acc;
}

// ---------------- transpose conv: parity-class blocking + 8-co tiling ----------------
__global__ void tconv_kernel(const float* __restrict__ tw, const float* __restrict__ bias,
                             float* __restrict__ out) {
    __shared__ float ws[8*576];
    int co0 = blockIdx.y*8;
    for (int idx = threadIdx.x; idx < 8*576; idx += 256) {
        int co_l = idx/576, rem = idx%576, ci = rem/9, q = rem%9;
        ws[idx] = tw[((size_t)(ci*64 + co0 + co_l))*9 + q];
    }
    __syncthreads();

    int cls = blockIdx.z;
    int px = cls & 1, py = cls >> 1;
    int p2 = blockIdx.x*256 + threadIdx.x;
    int xw = p2 % HH;
    int yh = (p2 / HH) % HH;
    int b  = p2 / (HH*HH);
    int ow = 2*xw + px, oh = 2*yh + py;

    float acc[8];
    #pragma unroll
    for (int c = 0; c < 8; c++) acc[c] = bias[co0+c];

    const float* gbase = g_gT + (size_t)b*64*NN;
    #pragma unroll
    for (int kh = 0; kh < 3; kh++) {
        int t_ = oh + 1 - kh;
        if (t_ & 1) continue;
        int ih = t_ >> 1; if ((unsigned)ih >= HH) continue;
        #pragma unroll
        for (int kw = 0; kw < 3; kw++) {
            int u = ow + 1 - kw;
            if (u & 1) continue;
            int iw = u >> 1; if ((unsigned)iw >= HH) continue;
            const float* gp = gbase + ih*HH + iw;
            int qq = kh*3 + kw;
            #pragma unroll 8
            for (int ci = 0; ci < 64; ci++) {
                float gv = gp[(size_t)ci*NN];
                #pragma unroll
                for (int c = 0; c < 8; c++) acc[c] += gv * ws[c*576 + ci*9 + qq];
            }
        }
    }
    #pragma unroll
    for (int c = 0; c < 8; c++)
        out[((size_t)(b*64 + co0 + c))*(HIN*HIN) + oh*HIN + ow] = acc[c];
}

// ---------------- launcher ----------------
extern "C" void kernel_launch(void* const* d_in, const int* in_sizes, int n_in,
                              void* d_out, int out_size) {
    const float* x       = (const float*)d_in[0];
    const float* conv_w  = (const float*)d_in[1];
    const float* conv_b  = (const float*)d_in[2];
    const float* W1      = (const float*)d_in[3];
    const float* a1      = (const float*)d_in[4];
    const float* W2      = (const float*)d_in[5];
    const float* a2      = (const float*)d_in[6];
    const float* Wout    = (const float*)d_in[7];
    const float* aout    = (const float*)d_in[8];
    const float* tconv_w = (const float*)d_in[9];
    const float* tconv_b = (const float*)d_in[10];
    float* out = (float*)d_out;

    cudaFuncSetAttribute(knn_kernel, cudaFuncAttributeMaxDynamicSharedMemorySize,
                         KNN_SMEM_BYTES);

    conv_kernel<<<dim3(18, 8), 256>>>(x, conv_w, conv_b);
    stats_linear_kernel<<<NROWS/16, 256>>>(W1, W2, a1, a2, Wout, aout);
    knn_kernel<<<dim3(JSPLIT, 18, 2), 256, KNN_SMEM_BYTES>>>();
    gat_fused_kernel<<<NROWS/16, 256>>>(Wout);
    gat_out_kernel<<<NROWS/4, 256>>>();
    tconv_kernel<<<dim3(18, 8, 4), 256>>>(tconv_w, tconv_b, out);
}

// round 14
// speedup vs baseline: 1.1569x; 1.0978x over previous
#include <cuda_runtime.h>
#include <math.h>

#define BB 2
#define CIN 64
#define CC 64
#define HIN 96
#define HH 48
#define NN 2304
#define KK 7
#define NROWS 4608
#define JSPLIT 12
#define JT_PER 3            /* 36 j-tiles / JSPLIT */

#define KNN_SMEM_BYTES ((128*66 + 64*66 + 128*66) * 4)   /* 84480 */

// ---------------- scratch ----------------
__device__ float g_feat[NROWS*CC];
__device__ float g_sq[NROWS];
__device__ int   g_nbr[NROWS*KK];
__device__ unsigned long long g_cand[(size_t)NROWS*JSPLIT*KK];
__device__ float g_Wh1[NROWS*CC];
__device__ float g_Wh2[NROWS*CC];
__device__ float g_Who[NROWS*CC];
__device__ float g_gT[BB*CC*NN];
__device__ float g_s11[NROWS], g_s21[NROWS], g_s12[NROWS], g_s22[NROWS];
__device__ float g_so1[NROWS], g_so2[NROWS];
__device__ float g_vo[256];   // vo1[0:128] vo2[128:256]

// packed dual-lane FMA (Blackwell f32x2) — d += a*b elementwise on 2 floats
__device__ __forceinline__ void ffma2(unsigned long long& d,
                                      unsigned long long a, unsigned long long b) {
    asm("fma.rn.f32x2 %0, %1, %2, %0;" : "+l"(d) : "l"(a), "l"(b));
}

// ---------------- stage 1: stride-2 conv (1 px x 4 co per thread, 256 thr) ----------------
__global__ void conv_kernel(const float* __restrict__ x, const float* __restrict__ w,
                            const float* __restrict__ bias) {
    __shared__ float ws[4][576];
    int co0 = blockIdx.y * 4;
    for (int idx = threadIdx.x; idx < 4*576; idx += 256)
        ws[idx/576][idx%576] = w[co0*576 + idx];
    __syncthreads();

    int p = blockIdx.x*256 + threadIdx.x;   // [0, 4608)
    int b = p / NN;
    int n = p % NN;
    int ih0 = (n / HH)*2 - 1;
    int iw0 = (n % HH)*2 - 1;

    bool ok[9]; int off[9];
    #pragma unroll
    for (int kh = 0; kh < 3; kh++)
        #pragma unroll
        for (int kw = 0; kw < 3; kw++) {
            int ih = ih0 + kh, iw = iw0 + kw;
            bool o = ((unsigned)ih < HIN) && ((unsigned)iw < HIN);
            ok[kh*3+kw] = o;
            off[kh*3+kw] = o ? (ih*HIN + iw) : 0;
        }

    float acc[4];
    #pragma unroll
    for (int c = 0; c < 4; c++) acc[c] = bias[co0+c];

    const float* xp = x + (size_t)b*64*(HIN*HIN);
    for (int ci = 0; ci < 64; ci++, xp += HIN*HIN) {
        float xv[9];
        #pragma unroll
        for (int q = 0; q < 9; q++) xv[q] = ok[q] ? xp[off[q]] : 0.f;
        #pragma unroll
        for (int q = 0; q < 9; q++) {
            #pragma unroll
            for (int c = 0; c < 4; c++) acc[c] += xv[q]*ws[c][ci*9+q];
        }
    }
    float4* fp = (float4*)&g_feat[(size_t)p*64 + co0];
    fp[0] = make_float4(acc[0], acc[1], acc[2], acc[3]);
}

// ---------------- stage 2: Wh1/Wh2 GEMM + row norms/scores (+folded vecs) ----------------
__global__ void stats_linear_kernel(const float* __restrict__ W1, const float* __restrict__ W2,
                                    const float* __restrict__ a1, const float* __restrict__ a2,
                                    const float* __restrict__ Wout, const float* __restrict__ aout) {
    __shared__ float sf[16][64];
    __shared__ float sv[256];   // v1a[0:64] v1b[64:128] v2a[128:192] v2b[192:256]
    int r0 = blockIdx.x*16;
    for (int it = 0; it < 4; it++) {
        int idx = it*256 + threadIdx.x;
        sf[idx >> 6][idx & 63] = g_feat[(size_t)(r0 + (idx >> 6))*64 + (idx & 63)];
    }
    if (threadIdx.x < 64) {
        int k = threadIdx.x;
        float s=0.f,t=0.f,u=0.f,v=0.f;
        #pragma unroll 8
        for (int f = 0; f < 64; f++) {
            float w1 = W1[k*64+f]; s += w1*a1[f]; t += w1*a1[64+f];
            float w2 = W2[k*64+f]; u += w2*a2[f]; v += w2*a2[64+f];
        }
        sv[k]=s; sv[64+k]=t; sv[128+k]=u; sv[192+k]=v;
    }
    // block 0 additionally folds aout through Wout into g_vo (once for whole grid)
    if (blockIdx.x == 0 && threadIdx.x >= 128) {
        int k = threadIdx.x - 128;
        float s = 0.f, t2 = 0.f;
        #pragma unroll 8
        for (int ff = 0; ff < 64; ff++) {
            float wo = Wout[k*64+ff];
            s += wo*aout[ff]; t2 += wo*aout[64+ff];
        }
        g_vo[k] = s; g_vo[128+k] = t2;
    }
    __syncthreads();
    {
        int f = threadIdx.x & 63, rs = threadIdx.x >> 6;
        float a1r[4] = {0,0,0,0}, a2r[4] = {0,0,0,0};
        #pragma unroll 8
        for (int k = 0; k < 64; k++) {
            float w1 = W1[k*64+f], w2 = W2[k*64+f];
            #pragma unroll
            for (int r = 0; r < 4; r++) {
                float hv = sf[rs*4+r][k];
                a1r[r] += hv*w1; a2r[r] += hv*w2;
            }
        }
        #pragma unroll
        for (int r = 0; r < 4; r++) {
            int row = r0 + rs*4 + r;
            g_Wh1[(size_t)row*64+f] = a1r[r];
            g_Wh2[(size_t)row*64+f] = a2r[r];
        }
    }
    {
        int lr = threadIdx.x >> 4, ln = threadIdx.x & 15;
        float p0=0.f,p1=0.f,p2=0.f,p3=0.f,p4=0.f;
        #pragma unroll
        for (int q = 0; q < 4; q++) {
            int k = ln*4 + q;
            float hv = sf[lr][k];
            p0 += hv*hv;
            p1 += hv*sv[k];      p2 += hv*sv[64+k];
            p3 += hv*sv[128+k];  p4 += hv*sv[192+k];
        }
        #pragma unroll
        for (int off = 8; off; off >>= 1) {
            p0 += __shfl_xor_sync(0xffffffffu, p0, off);
            p1 += __shfl_xor_sync(0xffffffffu, p1, off);
            p2 += __shfl_xor_sync(0xffffffffu, p2, off);
            p3 += __shfl_xor_sync(0xffffffffu, p3, off);
            p4 += __shfl_xor_sync(0xffffffffu, p4, off);
        }
        if (ln == 0) {
            int row = r0 + lr;
            g_sq[row]  = p0;
            g_s11[row] = p1; g_s21[row] = p2;
            g_s12[row] = p3; g_s22[row] = p4;
        }
    }
}

// ---------------- fused dist + top-7: 128x64 tile, 8x4/thread, dynamic smem ----------------
__global__ void __launch_bounds__(256, 2) knn_kernel() {
    extern __shared__ __align__(16) float smem[];
    float (*As)[66] = (float(*)[66])smem;                     // 128 rows
    float (*Bs)[66] = (float(*)[66])(smem + 128*66);          // 64 rows
    float (*Ds)[66] = (float(*)[66])(smem + 128*66 + 64*66);  // 128 rows; later cand
    unsigned long long* cand = (unsigned long long*)&Ds[0][0];  // 14336B < 33792B

    int s = blockIdx.x, itile = blockIdx.y, b = blockIdx.z;
    int i0 = itile*128;
    int t = threadIdx.x;
    for (int q = 0; q < 32; q++) {
        int idx = q*256 + t; int r = idx>>6, c = idx&63;
        As[r][c] = g_feat[(size_t)(b*NN + i0 + r)*64 + c];
    }
    int tx = t&15, ty = t>>4;
    float sqi[8];
    #pragma unroll
    for (int m = 0; m < 8; m++) sqi[m] = g_sq[b*NN + i0 + ty + 16*m];
    int srow = t>>1, sch = t&1;
    float lv[7]; int li[7];
    #pragma unroll
    for (int k = 0; k < 7; k++) { lv[k] = INFINITY; li[k] = 0x7fffffff; }

    for (int jt = 0; jt < JT_PER; jt++) {
        int j0 = (s*JT_PER + jt)*64;
        for (int q = 0; q < 16; q++) {
            int idx = q*256 + t; int r = idx>>6, c = idx&63;
            Bs[r][c] = g_feat[(size_t)(b*NN + j0 + r)*64 + c];
        }
        __syncthreads();                       // Bs ready; prev selection done (Ds free)
        unsigned long long acc2[8][4];
        #pragma unroll
        for (int mi = 0; mi < 8; mi++)
            #pragma unroll
            for (int mj = 0; mj < 4; mj++) acc2[mi][mj] = 0ull;
        #pragma unroll 4
        for (int c2 = 0; c2 < 32; c2++) {
            unsigned long long av[8], bv[4];
            #pragma unroll
            for (int m = 0; m < 8; m++)
                av[m] = *(const unsigned long long*)&As[ty+16*m][2*c2];
            #pragma unroll
            for (int m = 0; m < 4; m++)
                bv[m] = *(const unsigned long long*)&Bs[tx+16*m][2*c2];
            #pragma unroll
            for (int mi = 0; mi < 8; mi++)
                #pragma unroll
                for (int mj = 0; mj < 4; mj++)
                    ffma2(acc2[mi][mj], av[mi], bv[mj]);
        }
        float sqj[4];
        #pragma unroll
        for (int m = 0; m < 4; m++) sqj[m] = g_sq[b*NN + j0 + tx + 16*m];
        #pragma unroll
        for (int mi = 0; mi < 8; mi++)
            #pragma unroll
            for (int mj = 0; mj < 4; mj++) {
                float2 d = *(float2*)&acc2[mi][mj];
                float dot = d.x + d.y;
                Ds[ty+16*mi][tx+16*mj] = fmaxf(sqi[mi] + sqj[mj] - 2.f*dot, 0.f);
            }
        __syncthreads();                       // Ds ready; all GEMM reads of Bs done
        // per-thread candidates arrive in strictly increasing j: strict-< float
        // insertion preserves stable-argsort tie semantics.
        #pragma unroll
        for (int q = 0; q < 32; q++) {
            int jl = sch*32 + q;
            float v = Ds[srow][jl];
            if (v < lv[6]) {
                lv[6] = v; li[6] = j0 + jl;
                #pragma unroll
                for (int p = 6; p > 0; p--) {
                    bool sw = lv[p] < lv[p-1];
                    float tv = lv[p-1]; int ti = li[p-1];
                    lv[p-1] = sw ? lv[p] : lv[p-1];
                    li[p-1] = sw ? li[p] : li[p-1];
                    lv[p]   = sw ? tv : lv[p];
                    li[p]   = sw ? ti : li[p];
                }
            }
        }
    }
    __syncthreads();                           // selections done; Ds free for cand
    #pragma unroll
    for (int k = 0; k < 7; k++)
        cand[srow*14 + sch*7 + k] =
            ((unsigned long long)__float_as_uint(lv[k]) << 32) | (unsigned)li[k];
    __syncthreads();
    if (t < 128) {
        int p0 = 0, p1 = 0;
        unsigned long long* cA = &cand[t*14];
        unsigned long long* go = &g_cand[((size_t)(b*NN + i0 + t)*JSPLIT + s)*KK];
        #pragma unroll
        for (int k = 0; k < KK; k++) {
            unsigned long long v0 = p0 < 7 ? cA[p0] : ~0ull;
            unsigned long long v1 = p1 < 7 ? cA[7+p1] : ~0ull;
            if (v0 < v1) { go[k] = v0; p0++; }
            else         { go[k] = v1; p1++; }
        }
    }
}

// ---------------- fused: knn merge + head agg + out linear + scores (8 rows/block) ----------------
__global__ void gat_fused_kernel(const float* __restrict__ Wout) {
    __shared__ float sf[8][128];
    __shared__ int   jn[8][KK];
    __shared__ float e1[8][KK], e2[8][KK];
    __shared__ float vo[256];
    __shared__ unsigned long long sc[8][JSPLIT*KK];   // 8x84 u64 = 5376B
    int r0 = blockIdx.x*8;
    int g = threadIdx.x >> 6, f = threadIdx.x & 63;

    // parallel coalesced staging of candidates (8 rows x 84)
    for (int i = threadIdx.x; i < 8*JSPLIT*KK; i += 256)
        sc[i/(JSPLIT*KK)][i%(JSPLIT*KK)] = g_cand[(size_t)r0*JSPLIT*KK + i];
    vo[threadIdx.x] = g_vo[threadIdx.x];
    __syncthreads();

    // 12-way merge from smem (threads 0..7, one row each)
    if (threadIdx.x < 8) {
        int lr = threadIdx.x;
        int row = r0 + lr;
        int ptr[JSPLIT];
        #pragma unroll
        for (int q = 0; q < JSPLIT; q++) ptr[q] = 0;
        int bbase = (row / NN) * NN;
        for (int k = 0; k < KK; k++) {
            int bq = 0; unsigned long long bk = ~0ull;
            #pragma unroll
            for (int q = 0; q < JSPLIT; q++) {
                if (ptr[q] < KK) {
                    unsigned long long v = sc[lr][q*KK + ptr[q]];
                    if (v < bk) { bk = v; bq = q; }
                }
            }
            ptr[bq]++;
            int j = bbase + (int)(bk & 0xffffffffu);
            jn[lr][k] = j;
            g_nbr[row*KK + k] = j;             // for gat_out
        }
    }
    __syncthreads();

    #pragma unroll
    for (int rr = 0; rr < 2; rr++) {
        int lr = rr*4 + g;
        int row = r0 + lr;
        if (f < KK) {
            int j = jn[lr][f];
            float v1 = g_s11[row] + g_s21[j];
            float v2 = g_s12[row] + g_s22[j];
            e1[lr][f] = v1 > 0.f ? v1 : 0.2f*v1;
            e2[lr][f] = v2 > 0.f ? v2 : 0.2f*v2;
        }
    }
    __syncthreads();
    #pragma unroll
    for (int rr = 0; rr < 2; rr++) {
        int lr = rr*4 + g;
        float m1 = -INFINITY, m2 = -INFINITY;
        #pragma unroll
        for (int k = 0; k < KK; k++) { m1 = fmaxf(m1, e1[lr][k]); m2 = fmaxf(m2, e2[lr][k]); }
        float w1[KK], w2[KK], s1 = 0.f, s2 = 0.f;
        #pragma unroll
        for (int k = 0; k < KK; k++) {
            w1[k] = expf(e1[lr][k]-m1); s1 += w1[k];
            w2[k] = expf(e2[lr][k]-m2); s2 += w2[k];
        }
        float i1 = 1.f/s1, i2 = 1.f/s2;
        float acc1 = 0.f, acc2 = 0.f;
        #pragma unroll
        for (int k = 0; k < KK; k++) {
            int j = jn[lr][k];
            acc1 += (w1[k]*i1)*g_Wh1[(size_t)j*64+f];
            acc2 += (w2[k]*i2)*g_Wh2[(size_t)j*64+f];
        }
        acc1 = acc1 > 0.f ? acc1 : (expf(acc1)-1.f);
        acc2 = acc2 > 0.f ? acc2 : (expf(acc2)-1.f);
        sf[lr][f]      = acc1;
        sf[lr][64 + f] = acc2;
    }
    __syncthreads();
    {
        int rs = threadIdx.x >> 6;   // 0..3, 2 rows each
        float acc[2] = {0,0};
        #pragma unroll 8
        for (int k = 0; k < 128; k++) {
            float wv = Wout[k*64+f];
            #pragma unroll
            for (int r = 0; r < 2; r++) acc[r] += sf[rs*2+r][k]*wv;
        }
        #pragma unroll
        for (int r = 0; r < 2; r++)
            g_Who[(size_t)(r0 + rs*2 + r)*64+f] = acc[r];
    }
    {
        int lr = threadIdx.x >> 4, ln = threadIdx.x & 15;   // lr 0..15; rows only 0..7
        if (lr < 8) {
            float p1 = 0.f, p2 = 0.f;
            #pragma unroll
            for (int q = 0; q < 8; q++) {
                int k = ln*8 + q;
                float hv = sf[lr][k];
                p1 += hv*vo[k]; p2 += hv*vo[128+k];
            }
            #pragma unroll
            for (int off = 8; off; off >>= 1) {
                p1 += __shfl_xor_sync(0xffffffffu, p1, off);
                p2 += __shfl_xor_sync(0xffffffffu, p2, off);
            }
            if (ln == 0) {
                g_so1[r0 + lr] = p1;
                g_so2[r0 + lr] = p2;
            }
        }
    }
}

// ---------------- output aggregation -> g_gT ----------------
__global__ void gat_out_kernel() {
    int g = threadIdx.x >> 6, f = threadIdx.x & 63;
    int row = blockIdx.x*4 + g;
    __shared__ int   jn[4][KK];
    __shared__ float ee[4][KK];
    if (f < KK) {
        int j = g_nbr[row*KK + f];
        jn[g][f] = j;
        float v = g_so1[row] + g_so2[j];
        ee[g][f] = v > 0.f ? v : 0.2f*v;
    }
    __syncthreads();
    float mx = -INFINITY;
    #pragma unroll
    for (int k = 0; k < KK; k++) mx = fmaxf(mx, ee[g][k]);
    float wk[KK], sum = 0.f;
    #pragma unroll
    for (int k = 0; k < KK; k++) { wk[k] = expf(ee[g][k]-mx); sum += wk[k]; }
    float inv = 1.f/sum, acc = 0.f;
    #pragma unroll
    for (int k = 0; k < KK; k++) acc += (wk[k]*inv)*g_Who[(size_t)jn[g][k]*64+f];
    acc = acc > 0.f ? acc : (expf(acc)-1.f);
    int b = row / NN, n = row % NN;
    g_gT[(size_t)(b*64 + f)*NN + n] = acc;
}

// ---------------- transpose conv: parity-class blocking + 8-co tiling ----------------
__global__ void tconv_kernel(const float* __restrict__ tw, const float* __restrict__ bias,
                             float* __restrict__ out) {
    __shared__ float ws[8*576];
    int co0 = blockIdx.y*8;
    for (int idx = threadIdx.x; idx < 8*576; idx += 256) {
        int co_l = idx/576, rem = idx%576, ci = rem/9, q = rem%9;
        ws[idx] = tw[((size_t)(ci*64 + co0 + co_l))*9 + q];
    }
    __syncthreads();

    int cls = blockIdx.z;
    int px = cls & 1, py = cls >> 1;
    int p2 = blockIdx.x*256 + threadIdx.x;
    int xw = p2 % HH;
    int yh = (p2 / HH) % HH;
    int b  = p2 / (HH*HH);
    int ow = 2*xw + px, oh = 2*yh + py;

    float acc[8];
    #pragma unroll
    for (int c = 0; c < 8; c++) acc[c] = bias[co0+c];

    const float* gbase = g_gT + (size_t)b*64*NN;
    #pragma unroll
    for (int kh = 0; kh < 3; kh++) {
        int t_ = oh + 1 - kh;
        if (t_ & 1) continue;
        int ih = t_ >> 1; if ((unsigned)ih >= HH) continue;
        #pragma unroll
        for (int kw = 0; kw < 3; kw++) {
            int u = ow + 1 - kw;
            if (u & 1) continue;
            int iw = u >> 1; if ((unsigned)iw >= HH) continue;
            const float* gp = gbase + ih*HH + iw;
            int qq = kh*3 + kw;
            #pragma unroll 8
            for (int ci = 0; ci < 64; ci++) {
                float gv = gp[(size_t)ci*NN];
                #pragma unroll
                for (int c = 0; c < 8; c++) acc[c] += gv * ws[c*576 + ci*9 + qq];
            }
        }
    }
    #pragma unroll
    for (int c = 0; c < 8; c++)
        out[((size_t)(b*64 + co0 + c))*(HIN*HIN) + oh*HIN + ow] = acc[c];
}

// ---------------- launcher ----------------
extern "C" void kernel_launch(void* const* d_in, const int* in_sizes, int n_in,
                              void* d_out, int out_size) {
    const float* x       = (const float*)d_in[0];
    const float* conv_w  = (const float*)d_in[1];
    const float* conv_b  = (const float*)d_in[2];
    const float* W1      = (const float*)d_in[3];
    const float* a1      = (const float*)d_in[4];
    const float* W2      = (const float*)d_in[5];
    const float* a2      = (const float*)d_in[6];
    const float* Wout    = (const float*)d_in[7];
    const float* aout    = (const float*)d_in[8];
    const float* tconv_w = (const float*)d_in[9];
    const float* tconv_b = (const float*)d_in[10];
    float* out = (float*)d_out;

    cudaFuncSetAttribute(knn_kernel, cudaFuncAttributeMaxDynamicSharedMemorySize,
                         KNN_SMEM_BYTES);

    conv_kernel<<<dim3(18, 16), 256>>>(x, conv_w, conv_b);
    stats_linear_kernel<<<NROWS/16, 256>>>(W1, W2, a1, a2, Wout, aout);
    knn_kernel<<<dim3(JSPLIT, 18, 2), 256, KNN_SMEM_BYTES>>>();
    gat_fused_kernel<<<NROWS/8, 256>>>(Wout);
    gat_out_kernel<<<NROWS/4, 256>>>();
    tconv_kernel<<<dim3(18, 8, 4), 256>>>(tconv_w, tconv_b, out);
}